// round 4
// baseline (speedup 1.0000x reference)
#include <cuda_runtime.h>

#define BB 4096
#define TT 400
#define CC 42
#define HH 16
#define SCALE 2.885390081777927f  // 2 * log2(e), folded into U and recurrent weights

// U[b][t][i] scalar f32, pre-scaled by SCALE, bias0 folded in. 104.9 MB.
__device__ __align__(16) float g_Uf[(size_t)BB * TT * HH];

// ---------- f32x2 helpers (kernel A) ----------
__device__ __forceinline__ unsigned long long pk2(float lo, float hi) {
    unsigned long long r;
    asm("mov.b64 %0, {%1, %2};" : "=l"(r) : "f"(lo), "f"(hi));
    return r;
}
__device__ __forceinline__ unsigned long long fma2(unsigned long long a, unsigned long long b,
                                                   unsigned long long c) {
    unsigned long long d;
    asm("fma.rn.f32x2 %0, %1, %2, %3;" : "=l"(d) : "l"(a), "l"(b), "l"(c));
    return d;
}

// ---------- Kernel A: U[b][t][:] = SCALE*(bias0 + W_ih0 @ x[b,:,t]) ----------
// grid (25, 256), block 128. Warp = 2 batch-pairs x 16 t (proven coalesced load pattern).
// Output staged in smem, written to g_Uf fully coalesced (512B contiguous per warp-instr).
__global__ void __launch_bounds__(128) kA(const float* __restrict__ x,
                                          const float* __restrict__ Wih0,
                                          const float* __restrict__ bih0,
                                          const float* __restrict__ bhh0) {
    __shared__ __align__(16) unsigned long long swd[CC][HH];      // duplicated scaled weights
    __shared__ unsigned long long sb[HH];
    __shared__ __align__(16) unsigned long long sstage[128][18];  // [ploc*16+tl][i] pairs, padded

    int tid = threadIdx.x;
    for (int k = tid; k < CC * HH; k += 128) {
        int c = k >> 4, i = k & 15;
        float wv = SCALE * Wih0[i * CC + c];
        swd[c][i] = pk2(wv, wv);
    }
    if (tid < HH) {
        float b = SCALE * (bih0[tid] + bhh0[tid]);
        sb[tid] = pk2(b, b);
    }
    __syncthreads();

    int tc = blockIdx.x;    // 0..24
    int bblk = blockIdx.y;  // 0..255
    int w = tid >> 5, lane = tid & 31;
    int s = lane >> 4, tl = lane & 15;
    int ploc = w * 2 + s;
    int p = bblk * 8 + ploc;
    int t = tc * 16 + tl;

    const float* xb0 = x + (size_t)(2 * p) * (CC * TT) + t;
    const float* xb1 = xb0 + (CC * TT);

    unsigned long long u[16];
#pragma unroll
    for (int i = 0; i < 16; i++) u[i] = sb[i];

#pragma unroll 7
    for (int c = 0; c < CC; c++) {
        float xa = xb0[c * TT];
        float xb = xb1[c * TT];
        unsigned long long xp = pk2(xa, xb);
        const ulonglong2* wp = (const ulonglong2*)&swd[c][0];
#pragma unroll
        for (int k = 0; k < 8; k++) {
            ulonglong2 w2 = wp[k];
            u[2 * k]     = fma2(w2.x, xp, u[2 * k]);
            u[2 * k + 1] = fma2(w2.y, xp, u[2 * k + 1]);
        }
    }

    // stage into smem
    {
        int row = ploc * 16 + tl;
        ulonglong2* st = (ulonglong2*)&sstage[row][0];
#pragma unroll
        for (int k = 0; k < 8; k++) st[k] = make_ulonglong2(u[2 * k], u[2 * k + 1]);
    }
    __syncthreads();

    // scalar copy-out: 1024 float4 per block, consecutive tid -> consecutive global float4
#pragma unroll
    for (int k = 0; k < 8; k++) {
        int f = tid + 128 * k;
        int i4 = f & 3;
        int tl2 = (f >> 2) & 15;
        int bl = f >> 6;  // local batch 0..15
        int row = (bl >> 1) * 16 + tl2;
        int half = bl & 1;
        const float* sp = ((const float*)&sstage[row][0]) + half;  // stride-2 floats
        float4 v = make_float4(sp[(i4 * 4 + 0) * 2], sp[(i4 * 4 + 1) * 2],
                               sp[(i4 * 4 + 2) * 2], sp[(i4 * 4 + 3) * 2]);
        size_t gb = (size_t)(bblk * 16 + bl);
        size_t gt = (size_t)(tc * 16 + tl2);
        *(float4*)(g_Uf + (gb * TT + gt) * 16 + i4 * 4) = v;
    }
}

// tanh with pre-scaled argument: z = 2*log2(e)*x  ->  tanh(x) = 1 - 2/(1+2^z)
#define TANH_PRE(H, Z)                                          \
    {                                                           \
        float _e, _r;                                           \
        asm("ex2.approx.f32 %0, %1;" : "=f"(_e) : "f"(Z));      \
        asm("rcp.approx.f32 %0, %1;" : "=f"(_r) : "f"(_e + 1.0f)); \
        (H) = fmaf(-2.0f, _r, 1.0f);                            \
    }

// ---------- Kernel B: lagged dual-layer recurrence, ONE exchange/step, 2048 warps ----------
// warp = 2 batches (s), lane = (i, s). Each step m computes h0(m) AND h1(m-1) in parallel
// (h1 lagged one step: depends only on h0(m-1), h1(m-2) = previous exchange), then a single
// STS.64 + syncwarp + 8 broadcast LDS.128 distributes both.
__global__ void __launch_bounds__(128) kB(const float* __restrict__ h0in,
                                          const float* __restrict__ Whh0,
                                          const float* __restrict__ Wih1,
                                          const float* __restrict__ Whh1,
                                          const float* __restrict__ bih1,
                                          const float* __restrict__ bhh1,
                                          const float* __restrict__ Wfc,
                                          const float* __restrict__ bfc,
                                          float* __restrict__ out) {
    __shared__ __align__(16) float2 sh[4][2][16];  // [warp][s][i] = {h0, h1}

    int tid = threadIdx.x;
    int w = tid >> 5;
    int lane = tid & 31;
    int i = lane & 15;
    int s = lane >> 4;
    int p = blockIdx.x * 4 + w;  // warp id 0..2047
    int b = 2 * p + s;           // batch 0..4095

    float WH0[16], WI1[16], WH1[16];
#pragma unroll
    for (int j = 0; j < 16; j++) {
        WH0[j] = SCALE * Whh0[i * 16 + j];
        WI1[j] = SCALE * Wih1[i * 16 + j];
        WH1[j] = SCALE * Whh1[i * 16 + j];
    }
    float b1s = SCALE * (bih1[i] + bhh1[i]);

    float h0a[16], h1a[16];
#pragma unroll
    for (int j = 0; j < 16; j++) {
        h0a[j] = h0in[b * 16 + j];
        h1a[j] = h0in[BB * HH + b * 16 + j];
    }
    float h1init = h1a[i];

    const float* up = g_Uf + ((size_t)b * TT) * 16 + i;
    const float* uend = up + (size_t)399 * 16;

    float2* myh = &sh[w][s][i];
    const float4* hrd = (const float4*)&sh[w][s][0];

#define KB_STEP(UC, FIRST)                                                     \
    {                                                                          \
        float a0 = fmaf(WH0[0], h0a[0], (UC));                                 \
        float a1 = WH0[1] * h0a[1];                                            \
        float c0 = fmaf(WI1[0], h0a[0], b1s);                                  \
        float c1 = WI1[1] * h0a[1];                                            \
        float c2 = WH1[0] * h1a[0];                                            \
        float c3 = WH1[1] * h1a[1];                                            \
        a0 = fmaf(WH0[2], h0a[2], a0);   a1 = fmaf(WH0[3], h0a[3], a1);        \
        c0 = fmaf(WI1[2], h0a[2], c0);   c1 = fmaf(WI1[3], h0a[3], c1);        \
        c2 = fmaf(WH1[2], h1a[2], c2);   c3 = fmaf(WH1[3], h1a[3], c3);        \
        a0 = fmaf(WH0[4], h0a[4], a0);   a1 = fmaf(WH0[5], h0a[5], a1);        \
        c0 = fmaf(WI1[4], h0a[4], c0);   c1 = fmaf(WI1[5], h0a[5], c1);        \
        c2 = fmaf(WH1[4], h1a[4], c2);   c3 = fmaf(WH1[5], h1a[5], c3);        \
        a0 = fmaf(WH0[6], h0a[6], a0);   a1 = fmaf(WH0[7], h0a[7], a1);        \
        c0 = fmaf(WI1[6], h0a[6], c0);   c1 = fmaf(WI1[7], h0a[7], c1);        \
        c2 = fmaf(WH1[6], h1a[6], c2);   c3 = fmaf(WH1[7], h1a[7], c3);        \
        a0 = fmaf(WH0[8], h0a[8], a0);   a1 = fmaf(WH0[9], h0a[9], a1);        \
        c0 = fmaf(WI1[8], h0a[8], c0);   c1 = fmaf(WI1[9], h0a[9], c1);        \
        c2 = fmaf(WH1[8], h1a[8], c2);   c3 = fmaf(WH1[9], h1a[9], c3);        \
        a0 = fmaf(WH0[10], h0a[10], a0); a1 = fmaf(WH0[11], h0a[11], a1);      \
        c0 = fmaf(WI1[10], h0a[10], c0); c1 = fmaf(WI1[11], h0a[11], c1);      \
        c2 = fmaf(WH1[10], h1a[10], c2); c3 = fmaf(WH1[11], h1a[11], c3);      \
        a0 = fmaf(WH0[12], h0a[12], a0); a1 = fmaf(WH0[13], h0a[13], a1);      \
        c0 = fmaf(WI1[12], h0a[12], c0); c1 = fmaf(WI1[13], h0a[13], c1);      \
        c2 = fmaf(WH1[12], h1a[12], c2); c3 = fmaf(WH1[13], h1a[13], c3);      \
        a0 = fmaf(WH0[14], h0a[14], a0); a1 = fmaf(WH0[15], h0a[15], a1);      \
        c0 = fmaf(WI1[14], h0a[14], c0); c1 = fmaf(WI1[15], h0a[15], c1);      \
        c2 = fmaf(WH1[14], h1a[14], c2); c3 = fmaf(WH1[15], h1a[15], c3);      \
        float z0 = a0 + a1;                                                    \
        float h0n;                                                             \
        TANH_PRE(h0n, z0);                                                     \
        float z1 = (c0 + c1) + (c2 + c3);                                      \
        float h1n;                                                             \
        TANH_PRE(h1n, z1);                                                     \
        if (FIRST) h1n = h1init;                                               \
        *myh = make_float2(h0n, h1n);                                          \
        __syncwarp();                                                          \
        float4 q0 = hrd[0], q1 = hrd[1], q2 = hrd[2], q3 = hrd[3];             \
        float4 q4 = hrd[4], q5 = hrd[5], q6 = hrd[6], q7 = hrd[7];             \
        h0a[0] = q0.x;  h1a[0] = q0.y;  h0a[1] = q0.z;  h1a[1] = q0.w;         \
        h0a[2] = q1.x;  h1a[2] = q1.y;  h0a[3] = q1.z;  h1a[3] = q1.w;         \
        h0a[4] = q2.x;  h1a[4] = q2.y;  h0a[5] = q2.z;  h1a[5] = q2.w;         \
        h0a[6] = q3.x;  h1a[6] = q3.y;  h0a[7] = q3.z;  h1a[7] = q3.w;         \
        h0a[8] = q4.x;  h1a[8] = q4.y;  h0a[9] = q4.z;  h1a[9] = q4.w;         \
        h0a[10] = q5.x; h1a[10] = q5.y; h0a[11] = q5.z; h1a[11] = q5.w;        \
        h0a[12] = q6.x; h1a[12] = q6.y; h0a[13] = q6.z; h1a[13] = q6.w;        \
        h0a[14] = q7.x; h1a[14] = q7.y; h0a[15] = q7.z; h1a[15] = q7.w;        \
    }

    // Iterations m = 0..400 (401 total). Step m computes h0(m) and h1(m-1).
    // m=0: h1 output overridden with the given layer-1 initial state.
    // m=400: h0(400) is junk (U clamped), discarded; h1(399) is the result.
    // U prefetched 2 steps ahead (DRAM latency cover).
    float ubA = up[0];            // U(0)
    float ubB = up[16];           // U(1)
    const float* upf = up + 32;   // next to load: U(2)

    {
        float tmp;
        {
            const float* q = (upf > uend) ? uend : upf;
            tmp = *q;
            upf += 16;
        }
        KB_STEP(ubA, true);  // m = 0
        ubA = tmp;           // U(2)
    }
#pragma unroll 1
    for (int k = 0; k < 200; k++) {
        {
            const float* q = (upf > uend) ? uend : upf;
            float tmp = *q;
            upf += 16;
            KB_STEP(ubB, false);  // m = 2k+1
            ubB = tmp;
        }
        {
            const float* q = (upf > uend) ? uend : upf;
            float tmp = *q;
            upf += 16;
            KB_STEP(ubA, false);  // m = 2k+2
            ubA = tmp;
        }
    }
#undef KB_STEP

    // final FC (NC=2): h1a[] now holds h1(399) for batch b
    if (i < 2) {
        float acc = bfc[i];
#pragma unroll
        for (int j = 0; j < 16; j++) acc = fmaf(Wfc[i * 16 + j], h1a[j], acc);
        out[b * 2 + i] = acc;
    }
}

extern "C" void kernel_launch(void* const* d_in, const int* in_sizes, int n_in,
                              void* d_out, int out_size) {
    const float* x    = (const float*)d_in[0];
    const float* h0   = (const float*)d_in[1];
    const float* Wih0 = (const float*)d_in[2];
    const float* Whh0 = (const float*)d_in[3];
    const float* bih0 = (const float*)d_in[4];
    const float* bhh0 = (const float*)d_in[5];
    const float* Wih1 = (const float*)d_in[6];
    const float* Whh1 = (const float*)d_in[7];
    const float* bih1 = (const float*)d_in[8];
    const float* bhh1 = (const float*)d_in[9];
    const float* Wfc  = (const float*)d_in[10];
    const float* bfc  = (const float*)d_in[11];
    float* out = (float*)d_out;

    dim3 gA(25, 256);
    kA<<<gA, 128>>>(x, Wih0, bih0, bhh0);
    kB<<<512, 128>>>(h0, Whh0, Wih1, Whh1, bih1, bhh1, Wfc, bfc, out);
}

// round 5
// speedup vs baseline: 1.0660x; 1.0660x over previous
#include <cuda_runtime.h>

#define BB 4096
#define TT 400
#define CC 42
#define HH 16
#define SCALE 2.885390081777927f  // 2 * log2(e), folded into U, recurrent weights, bias1

// g_U[pair(2048)][t(400)][i(16)] as f32x2 (lo = even batch, hi = odd batch), pre-scaled.
__device__ __align__(16) unsigned long long g_U[2048ull * TT * 16];

// ---------- f32x2 helpers ----------
__device__ __forceinline__ unsigned long long pk2(float lo, float hi) {
    unsigned long long r;
    asm("mov.b64 %0, {%1, %2};" : "=l"(r) : "f"(lo), "f"(hi));
    return r;
}
__device__ __forceinline__ void up2(unsigned long long v, float& a, float& b) {
    asm("mov.b64 {%0, %1}, %2;" : "=f"(a), "=f"(b) : "l"(v));
}
__device__ __forceinline__ unsigned long long fma2(unsigned long long a, unsigned long long b,
                                                   unsigned long long c) {
    unsigned long long d;
    asm("fma.rn.f32x2 %0, %1, %2, %3;" : "=l"(d) : "l"(a), "l"(b), "l"(c));
    return d;
}
__device__ __forceinline__ unsigned long long add2(unsigned long long a, unsigned long long b) {
    unsigned long long d;
    asm("add.rn.f32x2 %0, %1, %2;" : "=l"(d) : "l"(a), "l"(b));
    return d;
}
// tanh with pre-scaled argument: z = 2*log2(e)*x  ->  tanh(x) = 1 - 2/(1+2^z)
__device__ __forceinline__ float tanh_pre(float z) {
    float e, r;
    asm("ex2.approx.f32 %0, %1;" : "=f"(e) : "f"(z));
    asm("rcp.approx.f32 %0, %1;" : "=f"(r) : "f"(e + 1.0f));
    return fmaf(-2.0f, r, 1.0f);
}
__device__ __forceinline__ unsigned long long tanh2_pre(unsigned long long z) {
    float a, b;
    up2(z, a, b);
    return pk2(tanh_pre(a), tanh_pre(b));
}

// ---------- Kernel A: U[p][t][:] = SCALE*(bias0 + W_ih0 @ x_t)  (R3 version, best) ----------
__global__ void __launch_bounds__(128) kA(const float* __restrict__ x,
                                          const float* __restrict__ Wih0,
                                          const float* __restrict__ bih0,
                                          const float* __restrict__ bhh0) {
    __shared__ __align__(16) unsigned long long swd[CC][HH];
    __shared__ unsigned long long sb[HH];
    __shared__ __align__(16) unsigned long long sstage[128][18];

    int tid = threadIdx.x;
    for (int k = tid; k < CC * HH; k += 128) {
        int c = k >> 4, i = k & 15;
        float wv = SCALE * Wih0[i * CC + c];
        swd[c][i] = pk2(wv, wv);
    }
    if (tid < HH) {
        float b = SCALE * (bih0[tid] + bhh0[tid]);
        sb[tid] = pk2(b, b);
    }
    __syncthreads();

    int tc = blockIdx.x;    // 0..24
    int bblk = blockIdx.y;  // 0..255
    int w = tid >> 5, lane = tid & 31;
    int s = lane >> 4, tl = lane & 15;
    int ploc = w * 2 + s;
    int p = bblk * 8 + ploc;
    int t = tc * 16 + tl;

    const float* xb0 = x + (size_t)(2 * p) * (CC * TT) + t;
    const float* xb1 = xb0 + (CC * TT);

    unsigned long long u[16];
#pragma unroll
    for (int i = 0; i < 16; i++) u[i] = sb[i];

#pragma unroll 14
    for (int c = 0; c < CC; c++) {
        float xa = xb0[c * TT];
        float xb = xb1[c * TT];
        unsigned long long xp = pk2(xa, xb);
        const ulonglong2* wp = (const ulonglong2*)&swd[c][0];
#pragma unroll
        for (int k = 0; k < 8; k++) {
            ulonglong2 w2 = wp[k];
            u[2 * k]     = fma2(w2.x, xp, u[2 * k]);
            u[2 * k + 1] = fma2(w2.y, xp, u[2 * k + 1]);
        }
    }

    {
        int row = ploc * 16 + tl;
        ulonglong2* st = (ulonglong2*)&sstage[row][0];
#pragma unroll
        for (int k = 0; k < 8; k++) st[k] = make_ulonglong2(u[2 * k], u[2 * k + 1]);
    }
    __syncthreads();

    // coalesced copy to g_U: warp w handles ploc = 2w, 2w+1; each chunk = 16 rows x 128B
#pragma unroll
    for (int cc = 0; cc < 2; cc++) {
        int pl2 = w * 2 + cc;
        unsigned long long* gdst = g_U + ((size_t)(bblk * 8 + pl2) * TT + tc * 16) * 16;
#pragma unroll
        for (int j = 0; j < 4; j++) {
            int g = j * 64 + lane * 2;
            int r2 = g >> 4, col = g & 15;
            ulonglong2 v = *(const ulonglong2*)&sstage[pl2 * 16 + r2][col];
            *(ulonglong2*)&gdst[g] = v;
        }
    }
}

// ---------- Kernel B: lagged dual-layer recurrence, f32x2, ONE exchange/step ----------
// warp = 2 batch-pairs (slot s), lane = (i, s). Step m computes h0(m) and h1(m-1) in
// parallel ILP (h1 lagged one step), then one STS.128 + syncwarp + 16 LDS.128 exchange
// where element [s][i] = {h0 pair, h1 pair}. 1024 warps.
__global__ void __launch_bounds__(128) kB(const float* __restrict__ h0in,
                                          const float* __restrict__ Whh0,
                                          const float* __restrict__ Wih1,
                                          const float* __restrict__ Whh1,
                                          const float* __restrict__ bih1,
                                          const float* __restrict__ bhh1,
                                          const float* __restrict__ Wfc,
                                          const float* __restrict__ bfc,
                                          float* __restrict__ out) {
    __shared__ __align__(16) ulonglong2 sh[4][2][16];  // [warp][s][i] = {h0pair, h1pair}

    int tid = threadIdx.x;
    int w = tid >> 5;
    int lane = tid & 31;
    int i = lane & 15;
    int s = lane >> 4;
    int p = (blockIdx.x * 4 + w) * 2 + s;  // pair 0..2047
    int b0 = 2 * p, b1 = b0 + 1;

    // duplicated, pre-scaled weight rows
    unsigned long long WH0[16], WI1[16], WH1[16];
#pragma unroll
    for (int j = 0; j < 16; j++) {
        float v0 = SCALE * Whh0[i * 16 + j];
        float v1 = SCALE * Wih1[i * 16 + j];
        float v2 = SCALE * Whh1[i * 16 + j];
        WH0[j] = pk2(v0, v0);
        WI1[j] = pk2(v1, v1);
        WH1[j] = pk2(v2, v2);
    }
    float b1f = SCALE * (bih1[i] + bhh1[i]);
    const unsigned long long B1S = pk2(b1f, b1f);

    // initial hidden states (h0in layout (2, B, H))
    unsigned long long h0a[16], h1a[16];
#pragma unroll
    for (int j = 0; j < 16; j++) {
        h0a[j] = pk2(h0in[b0 * 16 + j], h0in[b1 * 16 + j]);
        h1a[j] = pk2(h0in[BB * HH + b0 * 16 + j], h0in[BB * HH + b1 * 16 + j]);
    }
    unsigned long long h1init = h1a[i];

    const unsigned long long* up = g_U + (size_t)p * TT * 16 + i;
    const unsigned long long* uend = up + (size_t)399 * 16;

    ulonglong2* myh = &sh[w][s][i];
    const ulonglong2* hrd = &sh[w][s][0];

#define KB_STEP(UC, FIRST)                                                       \
    {                                                                            \
        unsigned long long a0 = fma2(WH0[0], h0a[0], (UC));                      \
        unsigned long long a1 = fma2(WH0[1], h0a[1], 0ull);                      \
        unsigned long long c0 = fma2(WI1[0], h0a[0], B1S);                       \
        unsigned long long c1 = fma2(WI1[1], h0a[1], 0ull);                      \
        unsigned long long c2 = fma2(WH1[0], h1a[0], 0ull);                      \
        unsigned long long c3 = fma2(WH1[1], h1a[1], 0ull);                      \
        a0 = fma2(WH0[2], h0a[2], a0);   a1 = fma2(WH0[3], h0a[3], a1);          \
        c0 = fma2(WI1[2], h0a[2], c0);   c1 = fma2(WI1[3], h0a[3], c1);          \
        c2 = fma2(WH1[2], h1a[2], c2);   c3 = fma2(WH1[3], h1a[3], c3);          \
        a0 = fma2(WH0[4], h0a[4], a0);   a1 = fma2(WH0[5], h0a[5], a1);          \
        c0 = fma2(WI1[4], h0a[4], c0);   c1 = fma2(WI1[5], h0a[5], c1);          \
        c2 = fma2(WH1[4], h1a[4], c2);   c3 = fma2(WH1[5], h1a[5], c3);          \
        a0 = fma2(WH0[6], h0a[6], a0);   a1 = fma2(WH0[7], h0a[7], a1);          \
        c0 = fma2(WI1[6], h0a[6], c0);   c1 = fma2(WI1[7], h0a[7], c1);          \
        c2 = fma2(WH1[6], h1a[6], c2);   c3 = fma2(WH1[7], h1a[7], c3);          \
        a0 = fma2(WH0[8], h0a[8], a0);   a1 = fma2(WH0[9], h0a[9], a1);          \
        c0 = fma2(WI1[8], h0a[8], c0);   c1 = fma2(WI1[9], h0a[9], c1);          \
        c2 = fma2(WH1[8], h1a[8], c2);   c3 = fma2(WH1[9], h1a[9], c3);          \
        a0 = fma2(WH0[10], h0a[10], a0); a1 = fma2(WH0[11], h0a[11], a1);        \
        c0 = fma2(WI1[10], h0a[10], c0); c1 = fma2(WI1[11], h0a[11], c1);        \
        c2 = fma2(WH1[10], h1a[10], c2); c3 = fma2(WH1[11], h1a[11], c3);        \
        a0 = fma2(WH0[12], h0a[12], a0); a1 = fma2(WH0[13], h0a[13], a1);        \
        c0 = fma2(WI1[12], h0a[12], c0); c1 = fma2(WI1[13], h0a[13], c1);        \
        c2 = fma2(WH1[12], h1a[12], c2); c3 = fma2(WH1[13], h1a[13], c3);        \
        a0 = fma2(WH0[14], h0a[14], a0); a1 = fma2(WH0[15], h0a[15], a1);        \
        c0 = fma2(WI1[14], h0a[14], c0); c1 = fma2(WI1[15], h0a[15], c1);        \
        c2 = fma2(WH1[14], h1a[14], c2); c3 = fma2(WH1[15], h1a[15], c3);        \
        unsigned long long h0n = tanh2_pre(add2(a0, a1));                        \
        unsigned long long h1n = tanh2_pre(add2(add2(c0, c1), add2(c2, c3)));    \
        if (FIRST) h1n = h1init;                                                 \
        *myh = make_ulonglong2(h0n, h1n);                                        \
        __syncwarp();                                                            \
        {                                                                        \
            ulonglong2 q;                                                        \
            q = hrd[0];  h0a[0] = q.x;  h1a[0] = q.y;                            \
            q = hrd[1];  h0a[1] = q.x;  h1a[1] = q.y;                            \
            q = hrd[2];  h0a[2] = q.x;  h1a[2] = q.y;                            \
            q = hrd[3];  h0a[3] = q.x;  h1a[3] = q.y;                            \
            q = hrd[4];  h0a[4] = q.x;  h1a[4] = q.y;                            \
            q = hrd[5];  h0a[5] = q.x;  h1a[5] = q.y;                            \
            q = hrd[6];  h0a[6] = q.x;  h1a[6] = q.y;                            \
            q = hrd[7];  h0a[7] = q.x;  h1a[7] = q.y;                            \
            q = hrd[8];  h0a[8] = q.x;  h1a[8] = q.y;                            \
            q = hrd[9];  h0a[9] = q.x;  h1a[9] = q.y;                            \
            q = hrd[10]; h0a[10] = q.x; h1a[10] = q.y;                           \
            q = hrd[11]; h0a[11] = q.x; h1a[11] = q.y;                           \
            q = hrd[12]; h0a[12] = q.x; h1a[12] = q.y;                           \
            q = hrd[13]; h0a[13] = q.x; h1a[13] = q.y;                           \
            q = hrd[14]; h0a[14] = q.x; h1a[14] = q.y;                           \
            q = hrd[15]; h0a[15] = q.x; h1a[15] = q.y;                           \
        }                                                                        \
    }

    // Iterations m = 0..400 (401 total): step m produces h0(m) and h1(m-1).
    // m=0: h1 output overridden with layer-1 initial state (h1(-1) := h1_init).
    // m=400: h0(400) junk (U clamped), unused; h1(399) is the final state.
    unsigned long long ubA = up[0];
    unsigned long long ubB = up[16];
    const unsigned long long* upf = up + 32;

    {
        const unsigned long long* q = (upf > uend) ? uend : upf;
        unsigned long long tmp = *q;
        upf += 16;
        KB_STEP(ubA, true);
        ubA = tmp;
    }
#pragma unroll 1
    for (int k = 0; k < 200; k++) {
        {
            const unsigned long long* q = (upf > uend) ? uend : upf;
            unsigned long long tmp = *q;
            upf += 16;
            KB_STEP(ubB, false);
            ubB = tmp;
        }
        {
            const unsigned long long* q = (upf > uend) ? uend : upf;
            unsigned long long tmp = *q;
            upf += 16;
            KB_STEP(ubA, false);
            ubA = tmp;
        }
    }
#undef KB_STEP

    // final FC (NC=2): h1a[] holds h1(399) pairs for (b0, b1)
    if (i < 2) {
        float bf = bfc[i];
        unsigned long long acc = pk2(bf, bf);
#pragma unroll
        for (int j = 0; j < 16; j++) {
            float wv = Wfc[i * 16 + j];
            acc = fma2(pk2(wv, wv), h1a[j], acc);
        }
        float lo, hi;
        up2(acc, lo, hi);
        out[b0 * 2 + i] = lo;
        out[b1 * 2 + i] = hi;
    }
}

extern "C" void kernel_launch(void* const* d_in, const int* in_sizes, int n_in,
                              void* d_out, int out_size) {
    const float* x    = (const float*)d_in[0];
    const float* h0   = (const float*)d_in[1];
    const float* Wih0 = (const float*)d_in[2];
    const float* Whh0 = (const float*)d_in[3];
    const float* bih0 = (const float*)d_in[4];
    const float* bhh0 = (const float*)d_in[5];
    const float* Wih1 = (const float*)d_in[6];
    const float* Whh1 = (const float*)d_in[7];
    const float* bih1 = (const float*)d_in[8];
    const float* bhh1 = (const float*)d_in[9];
    const float* Wfc  = (const float*)d_in[10];
    const float* bfc  = (const float*)d_in[11];
    float* out = (float*)d_out;

    dim3 gA(25, 256);
    kA<<<gA, 128>>>(x, Wih0, bih0, bhh0);
    kB<<<256, 128>>>(h0, Whh0, Wih1, Whh1, bih1, bhh1, Wfc, bfc, out);
}